// round 15
// baseline (speedup 1.0000x reference)
#include <cuda_runtime.h>
#include <cuda_fp16.h>
#include <stdint.h>

// ---------------- problem constants ----------------
#define T_  20
#define S_  128
#define B_  32
#define H_  256
#define E_  128
#define V_  32000
#define N_  (S_*T_)      // 2560
#define NM_ (S_*7)       // 896 masked steps
#define ROWS_ (N_*B_)    // 81920
#define RQ_  (S_*B_)     // 4096
#define BH_ (B_*H_)

// ---------------- output layout (floats) ----------------
#define OFF_OUT   0ull
#define OFF_MEM1  131072000ull
#define OFF_MEM2  131080192ull
#define OFF_MEM3  131088384ull
#define OFF_D1    131096576ull
#define OFF_D2    131129344ull
#define OFF_D3    131194880ull
#define OFF_REC1  131260416ull
#define OFF_REC2  152231936ull
#define OFF_REC3  173203456ull

// ---------------- device scratch (static, no runtime alloc) ----------------
__device__ float    g_cur1[RQ_*H_];      //  4 MB  layer-1 currents per token
__device__ float    g_cur [N_*B_*H_];    // 84 MB  currents (reused layer2/3)
__device__ __half   g_wouth[V_*H_];      // 16 MB  fp16 Wout
__device__ __half   g_poolh[RQ_*H_];     // spike counts 0..20, exact in fp16
__device__ float    g_wt2[H_*H_];        // W2 transposed [k][n]
__device__ float    g_wt3[H_*H_];        // W3 transposed [k][n]
__device__ unsigned g_mask[ROWS_*8];     // 2.6 MB spike bitmasks
__device__ float    g_xm[S_*E_];
__device__ float    g_xmrep[NM_*E_];
__device__ float    g_pm1[NM_*H_];       // SUMS of spikes over batch (ints in fp32)
__device__ float    g_pm2[NM_*H_];
__device__ float    g_pm3[NM_*H_];

// ---------------- merged prep: Wout->fp16, W2/W3 transpose, pm zero ----------------
__global__ void k_prep(const float* __restrict__ Wout,
                       const float* __restrict__ W2,
                       const float* __restrict__ W3) {
    int i = blockIdx.x * blockDim.x + threadIdx.x;
    if (i < V_*H_/2) {
        float2 w = ((const float2*)Wout)[i];
        ((__half2*)g_wouth)[i] = __floats2half2_rn(w.x, w.y);
    }
    if (i < H_*H_) {
        int n = i & 255, k = i >> 8;
        g_wt2[i] = W2[n*256 + k];
        g_wt3[i] = W3[n*256 + k];
    }
    if (i < NM_*H_) {
        g_pm1[i] = 0.f; g_pm2[i] = 0.f; g_pm3[i] = 0.f;
    }
}

// ---------------- layer-1 currents (fp32, sequential k) + batch-mean embedding ----------------
__global__ __launch_bounds__(256) void k_cur1(const int* __restrict__ x,
                                              const float* __restrict__ embed,
                                              const float* __restrict__ W1,
                                              const float* __restrict__ b1) {
    int s = blockIdx.x;
    __shared__ float semb[B_][E_];
    int tid = threadIdx.x;
    for (int u = tid; u < B_*E_; u += 256) {
        int b = u >> 7, e = u & 127;
        semb[b][e] = embed[(size_t)x[b*S_ + s] * E_ + e];
    }
    __syncthreads();
    int h = tid;
    float acc[B_];
#pragma unroll
    for (int b = 0; b < B_; b++) acc[b] = 0.f;
    for (int e = 0; e < E_; e++) {            // strictly increasing k, fp32 FMA
        float w = W1[h*E_ + e];
#pragma unroll
        for (int b = 0; b < B_; b++) acc[b] = fmaf(semb[b][e], w, acc[b]);
    }
    float bb = b1[h];
#pragma unroll
    for (int b = 0; b < B_; b++)
        g_cur1[((s*B_ + b) << 8) + h] = acc[b] + bb;

    if (tid < E_) {                            // batch mean, sequential b order
        float sum = 0.f;
#pragma unroll
        for (int b = 0; b < B_; b++) sum += semb[b][tid];
        g_xm[s*E_ + tid] = sum * (1.0f/32.0f);
    }
}

__global__ void k_xmrep() {
    int i = blockIdx.x * blockDim.x + threadIdx.x;
    if (i >= NM_*E_) return;
    int m = i / E_, e = i % E_;
    g_xmrep[i] = g_xm[(m/7)*E_ + e];
}

// ---------------- LIF recurrence: 1 warp/block, 2-token-ahead prefetch ----------
// mem = fma(0.85, mem, cur) - spk  (bit-identical ops/order to passing version)
// pm accumulation: atomicAdd of 0/1 floats; sums are exact ints <= 32.
template <int LAYER>
__global__ __launch_bounds__(32) void k_recur(float* __restrict__ rec,
                                              float* __restrict__ memOut) {
    const int lane = threadIdx.x;
    const int ht = blockIdx.x & 7;           // h tile
    const int b  = blockIdx.x >> 3;          // batch
    const int h  = ht*32 + lane;
    float* pm = (LAYER == 1) ? g_pm1 : (LAYER == 2 ? g_pm2 : g_pm3);

    float mem = 0.f, spk = 0.f;
    const size_t base = (size_t)b * H_ + h;

    constexpr int BUFN = (LAYER == 1) ? 1 : T_;
    float bA[BUFN], bB[BUFN], bC[BUFN];

    auto load_tok = [&](float* cb, int s) {
        if (s >= S_) return;
        if (LAYER == 1) cb[0] = g_cur1[(size_t)(s*B_ + b)*H_ + h];
        else {
#pragma unroll
            for (int t = 0; t < T_; t++) cb[t] = g_cur[base + (size_t)(s*T_ + t)*BH_];
        }
    };
    auto step_tok = [&](float* cb, int s) {
        if (s >= S_) return;
        size_t idx = base + (size_t)(s*T_)*BH_;
        float pc = 0.f;
#pragma unroll
        for (int t = 0; t < T_; t++) {
            float cur = (LAYER == 1) ? cb[0] : cb[t];
            mem = __fsub_rn(__fmaf_rn(0.85f, mem, cur), spk);
            bool fire = (mem > 1.0f);
            spk = fire ? 1.0f : 0.0f;
            rec[idx] = spk;
            if (LAYER <= 2) {
                unsigned msk = __ballot_sync(0xffffffffu, fire);
                if (lane == 0) g_mask[(size_t)((s*T_ + t)*B_ + b)*8 + ht] = msk;
            }
            if (LAYER == 3) pc += spk;
            if (t % 3 == 0)
                atomicAdd(&pm[(s*7 + t/3)*H_ + h], spk);  // exact int sum
            idx += BH_;
        }
        if (LAYER == 3) g_poolh[(size_t)(s*B_ + b)*H_ + h] = __float2half(pc);
    };

    load_tok(bA, 0);
    load_tok(bB, 1);
    for (int s = 0; s < S_; s += 3) {
        load_tok(bC, s+2);
        step_tok(bA, s);
        load_tok(bA, s+3);
        step_tok(bB, s+1);
        load_tok(bB, s+4);
        step_tok(bC, s+2);
    }
    memOut[base] = mem;
}

// ---------------- sparse mid GEMM: cur = spk @ W.T + bias ----------------
// Bitwise identical to dense sequential-k fp32: fmaf(0,w,a)=a, fmaf(1,w,a)=RN(a+w).
// 64 rows/block, each thread covers 8 rows x 8 n (two conflict-free LDS.128/bit).
__global__ __launch_bounds__(256) void k_gemm_sp(int wsel, const float* __restrict__ bias) {
    const float* WT = (wsel == 0) ? g_wt2 : g_wt3;   // [k][n]
    __shared__ float    sW[32*256];                  // 32 KB k-tile
    __shared__ unsigned sM[64];
    const int row0 = blockIdx.x * 64;
    const int tid = threadIdx.x;
    const int nlo = (tid & 31) * 4;       // n 0..127 quad
    const int rg  = (tid >> 5) * 8;       // 8 rows per thread

    float4 accL[8], accH[8];
#pragma unroll
    for (int r = 0; r < 8; r++) {
        accL[r] = make_float4(0.f,0.f,0.f,0.f);
        accH[r] = make_float4(0.f,0.f,0.f,0.f);
    }

    for (int kt = 0; kt < 8; kt++) {
        const float4* src = (const float4*)(WT + kt*32*256);
        float4* dst = (float4*)sW;
        for (int i = tid; i < 32*64; i += 256) dst[i] = src[i];
        if (tid < 64) sM[tid] = g_mask[(size_t)(row0 + tid)*8 + kt];
        __syncthreads();
#pragma unroll
        for (int r = 0; r < 8; r++) {
            unsigned m = sM[rg + r];
            float4 aL = accL[r], aH = accH[r];
            while (m) {
                int k = __ffs(m) - 1;            // ascending k: exact order
                m &= m - 1;
                const float* wrow = &sW[k*256];
                float4 w0 = *(const float4*)&wrow[nlo];
                float4 w1 = *(const float4*)&wrow[128 + nlo];
                aL.x = __fadd_rn(aL.x, w0.x); aL.y = __fadd_rn(aL.y, w0.y);
                aL.z = __fadd_rn(aL.z, w0.z); aL.w = __fadd_rn(aL.w, w0.w);
                aH.x = __fadd_rn(aH.x, w1.x); aH.y = __fadd_rn(aH.y, w1.y);
                aH.z = __fadd_rn(aH.z, w1.z); aH.w = __fadd_rn(aH.w, w1.w);
            }
            accL[r] = aL; accH[r] = aH;
        }
        __syncthreads();
    }
    float4 bL = *(const float4*)&bias[nlo];
    float4 bH = *(const float4*)&bias[128 + nlo];
#pragma unroll
    for (int r = 0; r < 8; r++) {
        size_t rowb = (size_t)(row0 + rg + r)*256;
        float4 oL = make_float4(accL[r].x+bL.x, accL[r].y+bL.y, accL[r].z+bL.z, accL[r].w+bL.w);
        float4 oH = make_float4(accH[r].x+bH.x, accH[r].y+bH.y, accH[r].z+bH.z, accH[r].w+bH.w);
        *(float4*)&g_cur[rowb + nlo]       = oL;
        *(float4*)&g_cur[rowb + 128 + nlo] = oH;
    }
}

// ---------------- fp16 mma.sync m16n8k16 + ldmatrix helpers ----------------
__device__ __forceinline__ void mma16816(float* d, const uint32_t* a, const uint32_t* b) {
    asm volatile(
        "mma.sync.aligned.m16n8k16.row.col.f32.f16.f16.f32 "
        "{%0,%1,%2,%3},{%4,%5,%6,%7},{%8,%9},{%0,%1,%2,%3};\n"
        : "+f"(d[0]), "+f"(d[1]), "+f"(d[2]), "+f"(d[3])
        : "r"(a[0]), "r"(a[1]), "r"(a[2]), "r"(a[3]), "r"(b[0]), "r"(b[1]));
}
__device__ __forceinline__ void ldsm_x4(uint32_t* r, const __half* p) {
    uint32_t a = (uint32_t)__cvta_generic_to_shared((void*)p);
    asm volatile("ldmatrix.sync.aligned.m8n8.x4.shared.b16 {%0,%1,%2,%3}, [%4];"
        : "=r"(r[0]), "=r"(r[1]), "=r"(r[2]), "=r"(r[3]) : "r"(a));
}

// ---------------- output GEMM: out = (counts . W)/20 + bout  (fp16, 256x128 tile) ----
// 8 warps as 4(m) x 2(n): 64m x 64n per warp; k-chunk 32 (smem 30.75 KB)
__global__ __launch_bounds__(256) void k_gemm_out(const float* __restrict__ bout,
                                                  float* __restrict__ out) {
    __shared__ __half sA[256*40];
    __shared__ __half sB[128*40];
    const int bn = blockIdx.x, bm = blockIdx.y;
    const int tid = threadIdx.x;
    const int warp = tid >> 5, lane = tid & 31;
    const int wm = warp >> 1, wn = warp & 1;       // 4 x 2 warps -> 64m x 64n each
    const int g = lane >> 2, tg = lane & 3;
    const int rsel = (lane & 7) | (lane & 8);      // ldmatrix row within 16
    const int csel = (lane >> 4) << 3;             // ldmatrix k-half select

    float acc[4][8][4] = {};

    for (int kc = 0; kc < 256; kc += 32) {
#pragma unroll
        for (int i = 0; i < 4; i++) {              // A: 256 rows x 32 halfs = 1024 uint4
            int u = tid + i*256;
            int row = u >> 2, c8 = (u & 3) * 8;
            *(uint4*)&sA[row*40 + c8] =
                *(const uint4*)&g_poolh[(size_t)(bm*256 + row)*256 + kc + c8];
        }
#pragma unroll
        for (int i = 0; i < 2; i++) {              // B: 128 rows x 32 halfs = 512 uint4
            int u = tid + i*256;
            int row = u >> 2, c8 = (u & 3) * 8;
            *(uint4*)&sB[row*40 + c8] =
                *(const uint4*)&g_wouth[(size_t)(bn*128 + row)*256 + kc + c8];
        }
        __syncthreads();
#pragma unroll
        for (int kk = 0; kk < 32; kk += 16) {
            uint32_t afr[4][4], bq[4][4];
#pragma unroll
            for (int mi = 0; mi < 4; mi++)
                ldsm_x4(afr[mi], &sA[(wm*64 + mi*16 + rsel)*40 + kk + csel]);
#pragma unroll
            for (int nb = 0; nb < 4; nb++)
                ldsm_x4(bq[nb], &sB[(wn*64 + nb*16 + rsel)*40 + kk + csel]);
#pragma unroll
            for (int mi = 0; mi < 4; mi++)
#pragma unroll
                for (int ni = 0; ni < 8; ni++) {
                    uint32_t bfr[2] = { bq[ni>>1][ni&1], bq[ni>>1][2 + (ni&1)] };
                    mma16816(acc[mi][ni], afr[mi], bfr);
                }
        }
        __syncthreads();
    }
    const float inv = 1.0f/20.0f;
#pragma unroll
    for (int mi = 0; mi < 4; mi++) {
        int r = bm*256 + wm*64 + mi*16 + g;   // r = s*32 + b ; (r&31)+8 stays < 32
        int s = r >> 5, bb = r & 31;
        size_t base  = (size_t)bb*(size_t)S_*V_ + (size_t)s*V_;
        size_t base8 = base + (size_t)8*(size_t)S_*V_;
#pragma unroll
        for (int ni = 0; ni < 8; ni++) {
            int v = bn*128 + wn*64 + ni*8 + tg*2;
            float b0 = bout[v], b1v = bout[v+1];
            float2 lo = make_float2(acc[mi][ni][0]*inv + b0, acc[mi][ni][1]*inv + b1v);
            float2 hi = make_float2(acc[mi][ni][2]*inv + b0, acc[mi][ni][3]*inv + b1v);
            *(float2*)&out[base  + v] = lo;
            *(float2*)&out[base8 + v] = hi;
        }
    }
}

// ---------------- STDP: d[o,i] = sum_m (A_POST*postmean)[m,o]*(A_PRE*premean)[m,i] ------
// pm arrays hold exact integer sums; *1/32 is exact (power of two) -> bit-identical.
__global__ void k_stdp(int sel, float* __restrict__ Dout, int I) {
    const float* Amat = (sel == 0) ? g_pm1 : (sel == 1 ? g_pm2 : g_pm3);
    const float* Bmat = (sel == 0) ? g_xmrep : (sel == 1 ? g_pm1 : g_pm2);
    const float bScale = (sel == 0) ? 1.0f : 0.03125f;
    int o = blockIdx.x;
    int i = threadIdx.x;
    float acc = 0.f;
    for (int m = 0; m < NM_; m++) {
        float a = __fmul_rn(-0.003f, __fmul_rn(__ldg(&Amat[m*H_ + o]), 0.03125f));
        float b = __fmul_rn( 0.005f, __fmul_rn(__ldg(&Bmat[m*I + i]), bScale));
        acc = fmaf(a, b, acc);
    }
    Dout[o*I + i] = acc;
}

// ---------------- launch ----------------
// RULE: never pass a __device__ symbol (g_*) as a kernel argument from here.
extern "C" void kernel_launch(void* const* d_in, const int* in_sizes, int n_in,
                              void* d_out, int out_size) {
    const int*   x     = (const int*)  d_in[0];
    const float* embed = (const float*)d_in[1];
    const float* W1    = (const float*)d_in[2];
    const float* b1    = (const float*)d_in[3];
    const float* W2    = (const float*)d_in[4];
    const float* b2    = (const float*)d_in[5];
    const float* W3    = (const float*)d_in[6];
    const float* b3    = (const float*)d_in[7];
    const float* Wout  = (const float*)d_in[8];
    const float* bout  = (const float*)d_in[9];
    float* out = (float*)d_out;

    (void)in_sizes; (void)n_in; (void)out_size;

    // merged prep: Wout fp16, W transpose, pm zero
    k_prep<<<(V_*H_/2 + 255)/256, 256>>>(Wout, W2, W3);

    // layer-1 currents (raw fp32, sequential k) + batch-mean embeddings
    k_cur1 <<<S_, 256>>>(x, embed, W1, b1);
    k_xmrep<<<(NM_*E_ + 255)/256, 256>>>();

    // layer 1
    k_recur<1><<<256, 32>>>(out + OFF_REC1, out + OFF_MEM1);
    // cur2 = spk1 @ W2.T + b2  (sparse, bit-exact sequential-k)
    k_gemm_sp<<<ROWS_/64, 256>>>(0, b2);
    // layer 2
    k_recur<2><<<256, 32>>>(out + OFF_REC2, out + OFF_MEM2);
    // cur3 = spk2 @ W3.T + b3
    k_gemm_sp<<<ROWS_/64, 256>>>(1, b3);
    // layer 3 (also builds pooled spike counts)
    k_recur<3><<<256, 32>>>(out + OFF_REC3, out + OFF_MEM3);

    // out = pooled @ Wout.T + bout  (plain fp16 tensor cores, /20 in epilogue)
    k_gemm_out<<<dim3(V_/128, RQ_/256), 256>>>(bout, out + OFF_OUT);

    // STDP
    k_stdp<<<H_, E_>>>(0, out + OFF_D1, E_);
    k_stdp<<<H_, H_>>>(1, out + OFF_D2, H_);
    k_stdp<<<H_, H_>>>(2, out + OFF_D3, H_);
}

// round 16
// speedup vs baseline: 1.2974x; 1.2974x over previous
#include <cuda_runtime.h>
#include <cuda_fp16.h>
#include <stdint.h>

// ---------------- problem constants ----------------
#define T_  20
#define S_  128
#define B_  32
#define H_  256
#define E_  128
#define V_  32000
#define N_  (S_*T_)      // 2560
#define NM_ (S_*7)       // 896 masked steps
#define ROWS_ (N_*B_)    // 81920
#define RQ_  (S_*B_)     // 4096
#define BH_ (B_*H_)

// ---------------- output layout (floats) ----------------
#define OFF_OUT   0ull
#define OFF_MEM1  131072000ull
#define OFF_MEM2  131080192ull
#define OFF_MEM3  131088384ull
#define OFF_D1    131096576ull
#define OFF_D2    131129344ull
#define OFF_D3    131194880ull
#define OFF_REC1  131260416ull
#define OFF_REC2  152231936ull
#define OFF_REC3  173203456ull

// ---------------- device scratch (static, no runtime alloc) ----------------
__device__ float    g_cur1[RQ_*H_];      //  4 MB  layer-1 currents per token
__device__ float    g_cur [N_*B_*H_];    // 84 MB  currents (reused layer2/3)
__device__ __half   g_wouth[V_*H_];      // 16 MB  fp16 Wout
__device__ __half   g_poolh[RQ_*H_];     // spike counts 0..20, exact in fp16
__device__ float    g_wt2[H_*H_];        // W2 transposed [k][n]
__device__ float    g_wt3[H_*H_];        // W3 transposed [k][n]
__device__ unsigned g_mask[ROWS_*8];     // 2.6 MB spike bitmasks
__device__ float    g_xm[S_*E_];
__device__ float    g_xmrep[NM_*E_];
__device__ float    g_pm1[NM_*H_];       // batch means at masked steps
__device__ float    g_pm2[NM_*H_];
__device__ float    g_pm3[NM_*H_];

// ---------------- merged prep: Wout->fp16, W2/W3 transpose ----------------
__global__ void k_prep(const float* __restrict__ Wout,
                       const float* __restrict__ W2,
                       const float* __restrict__ W3) {
    int i = blockIdx.x * blockDim.x + threadIdx.x;
    if (i < V_*H_/2) {
        float2 w = ((const float2*)Wout)[i];
        ((__half2*)g_wouth)[i] = __floats2half2_rn(w.x, w.y);
    }
    if (i < H_*H_) {
        int n = i & 255, k = i >> 8;
        g_wt2[i] = W2[n*256 + k];
        g_wt3[i] = W3[n*256 + k];
    }
}

// ---------------- layer-1 currents (fp32, sequential k) + batch-mean embedding ----------------
__global__ __launch_bounds__(256) void k_cur1(const int* __restrict__ x,
                                              const float* __restrict__ embed,
                                              const float* __restrict__ W1,
                                              const float* __restrict__ b1) {
    int s = blockIdx.x;
    __shared__ float semb[B_][E_];
    int tid = threadIdx.x;
    for (int u = tid; u < B_*E_; u += 256) {
        int b = u >> 7, e = u & 127;
        semb[b][e] = embed[(size_t)x[b*S_ + s] * E_ + e];
    }
    __syncthreads();
    int h = tid;
    float acc[B_];
#pragma unroll
    for (int b = 0; b < B_; b++) acc[b] = 0.f;
    for (int e = 0; e < E_; e++) {            // strictly increasing k, fp32 FMA
        float w = W1[h*E_ + e];
#pragma unroll
        for (int b = 0; b < B_; b++) acc[b] = fmaf(semb[b][e], w, acc[b]);
    }
    float bb = b1[h];
#pragma unroll
    for (int b = 0; b < B_; b++)
        g_cur1[((s*B_ + b) << 8) + h] = acc[b] + bb;

    if (tid < E_) {                            // batch mean, sequential b order
        float sum = 0.f;
#pragma unroll
        for (int b = 0; b < B_; b++) sum += semb[b][tid];
        g_xm[s*E_ + tid] = sum * (1.0f/32.0f);
    }
}

__global__ void k_xmrep() {
    int i = blockIdx.x * blockDim.x + threadIdx.x;
    if (i >= NM_*E_) return;
    int m = i / E_, e = i % E_;
    g_xmrep[i] = g_xm[(m/7)*E_ + e];
}

// ---------------- LIF recurrence: 1 warp/block, 2-token-ahead prefetch ----------
// mem = fma(0.85, mem, cur) - spk  (bit-identical ops/order to passing version)
template <int LAYER>
__global__ __launch_bounds__(32) void k_recur(float* __restrict__ rec,
                                              float* __restrict__ memOut) {
    const int lane = threadIdx.x;
    const int ht = blockIdx.x & 7;           // h tile
    const int b  = blockIdx.x >> 3;          // batch
    const int h  = ht*32 + lane;

    float mem = 0.f, spk = 0.f;
    const size_t base = (size_t)b * H_ + h;

    constexpr int BUFN = (LAYER == 1) ? 1 : T_;
    float bA[BUFN], bB[BUFN], bC[BUFN];

    auto load_tok = [&](float* cb, int s) {
        if (s >= S_) return;
        if (LAYER == 1) cb[0] = g_cur1[(size_t)(s*B_ + b)*H_ + h];
        else {
#pragma unroll
            for (int t = 0; t < T_; t++) cb[t] = g_cur[base + (size_t)(s*T_ + t)*BH_];
        }
    };
    auto step_tok = [&](float* cb, int s) {
        if (s >= S_) return;
        size_t idx = base + (size_t)(s*T_)*BH_;
        float pc = 0.f;
#pragma unroll
        for (int t = 0; t < T_; t++) {
            float cur = (LAYER == 1) ? cb[0] : cb[t];
            mem = __fsub_rn(__fmaf_rn(0.85f, mem, cur), spk);
            bool fire = (mem > 1.0f);
            spk = fire ? 1.0f : 0.0f;
            rec[idx] = spk;
            if (LAYER <= 2) {
                unsigned msk = __ballot_sync(0xffffffffu, fire);
                if (lane == 0) g_mask[(size_t)((s*T_ + t)*B_ + b)*8 + ht] = msk;
            }
            if (LAYER == 3) pc += spk;
            idx += BH_;
        }
        if (LAYER == 3) g_poolh[(size_t)(s*B_ + b)*H_ + h] = __float2half(pc);
    };

    load_tok(bA, 0);
    load_tok(bB, 1);
    for (int s = 0; s < S_; s += 3) {
        load_tok(bC, s+2);
        step_tok(bA, s);
        load_tok(bA, s+3);
        step_tok(bB, s+1);
        load_tok(bB, s+4);
        step_tok(bC, s+2);
    }
    memOut[base] = mem;
}

// ---------------- batch-mean spikes at masked steps (exact int sums) ----------------
__global__ __launch_bounds__(256) void k_pm(int sel, const float* __restrict__ rec) {
    float* pm = (sel == 0) ? g_pm1 : (sel == 1 ? g_pm2 : g_pm3);
    int m = blockIdx.x;               // 0..NM_-1
    int h = threadIdx.x;
    int step = (m/7)*T_ + (m%7)*3;
    const float* p = rec + (size_t)step*BH_ + h;
    float sum = 0.f;
#pragma unroll
    for (int b = 0; b < B_; b++) sum += p[(size_t)b*H_];   // 0/1 ints: order-free exact
    pm[m*H_ + h] = sum * (1.0f/32.0f);
}

// ---------------- sparse mid GEMM: cur = spk @ W.T + bias ----------------
// Bitwise identical to dense sequential-k fp32: fmaf(0,w,a)=a, fmaf(1,w,a)=RN(a+w).
// 64 rows/block, each thread covers 8 rows x 8 n (two conflict-free LDS.128/bit).
__global__ __launch_bounds__(256) void k_gemm_sp(int wsel, const float* __restrict__ bias) {
    const float* WT = (wsel == 0) ? g_wt2 : g_wt3;   // [k][n]
    __shared__ float    sW[32*256];                  // 32 KB k-tile
    __shared__ unsigned sM[64];
    const int row0 = blockIdx.x * 64;
    const int tid = threadIdx.x;
    const int nlo = (tid & 31) * 4;       // n 0..127 quad
    const int rg  = (tid >> 5) * 8;       // 8 rows per thread

    float4 accL[8], accH[8];
#pragma unroll
    for (int r = 0; r < 8; r++) {
        accL[r] = make_float4(0.f,0.f,0.f,0.f);
        accH[r] = make_float4(0.f,0.f,0.f,0.f);
    }

    for (int kt = 0; kt < 8; kt++) {
        const float4* src = (const float4*)(WT + kt*32*256);
        float4* dst = (float4*)sW;
        for (int i = tid; i < 32*64; i += 256) dst[i] = src[i];
        if (tid < 64) sM[tid] = g_mask[(size_t)(row0 + tid)*8 + kt];
        __syncthreads();
#pragma unroll
        for (int r = 0; r < 8; r++) {
            unsigned m = sM[rg + r];
            float4 aL = accL[r], aH = accH[r];
            while (m) {
                int k = __ffs(m) - 1;            // ascending k: exact order
                m &= m - 1;
                const float* wrow = &sW[k*256];
                float4 w0 = *(const float4*)&wrow[nlo];
                float4 w1 = *(const float4*)&wrow[128 + nlo];
                aL.x = __fadd_rn(aL.x, w0.x); aL.y = __fadd_rn(aL.y, w0.y);
                aL.z = __fadd_rn(aL.z, w0.z); aL.w = __fadd_rn(aL.w, w0.w);
                aH.x = __fadd_rn(aH.x, w1.x); aH.y = __fadd_rn(aH.y, w1.y);
                aH.z = __fadd_rn(aH.z, w1.z); aH.w = __fadd_rn(aH.w, w1.w);
            }
            accL[r] = aL; accH[r] = aH;
        }
        __syncthreads();
    }
    float4 bL = *(const float4*)&bias[nlo];
    float4 bH = *(const float4*)&bias[128 + nlo];
#pragma unroll
    for (int r = 0; r < 8; r++) {
        size_t rowb = (size_t)(row0 + rg + r)*256;
        float4 oL = make_float4(accL[r].x+bL.x, accL[r].y+bL.y, accL[r].z+bL.z, accL[r].w+bL.w);
        float4 oH = make_float4(accH[r].x+bH.x, accH[r].y+bH.y, accH[r].z+bH.z, accH[r].w+bH.w);
        *(float4*)&g_cur[rowb + nlo]       = oL;
        *(float4*)&g_cur[rowb + 128 + nlo] = oH;
    }
}

// ---------------- fp16 mma.sync m16n8k16 + ldmatrix helpers ----------------
__device__ __forceinline__ void mma16816(float* d, const uint32_t* a, const uint32_t* b) {
    asm volatile(
        "mma.sync.aligned.m16n8k16.row.col.f32.f16.f16.f32 "
        "{%0,%1,%2,%3},{%4,%5,%6,%7},{%8,%9},{%0,%1,%2,%3};\n"
        : "+f"(d[0]), "+f"(d[1]), "+f"(d[2]), "+f"(d[3])
        : "r"(a[0]), "r"(a[1]), "r"(a[2]), "r"(a[3]), "r"(b[0]), "r"(b[1]));
}
__device__ __forceinline__ void ldsm_x4(uint32_t* r, const __half* p) {
    uint32_t a = (uint32_t)__cvta_generic_to_shared((void*)p);
    asm volatile("ldmatrix.sync.aligned.m8n8.x4.shared.b16 {%0,%1,%2,%3}, [%4];"
        : "=r"(r[0]), "=r"(r[1]), "=r"(r[2]), "=r"(r[3]) : "r"(a));
}

// ---------------- output GEMM: out = (counts . W)/20 + bout ----------------
// 128x128 tile (R13 warp mapping), k-chunk 32, 2-stage cp.async pipeline.
__global__ __launch_bounds__(256) void k_gemm_out(const float* __restrict__ bout,
                                                  float* __restrict__ out) {
    __shared__ __half sA[2][128*40];
    __shared__ __half sB[2][128*40];
    const int bn = blockIdx.x, bm = blockIdx.y;
    const int tid = threadIdx.x;
    const int warp = tid >> 5, lane = tid & 31;
    const int wm = warp >> 1, wn = warp & 1;       // 4 x 2 warps -> 32m x 64n each
    const int g = lane >> 2, tg = lane & 3;
    const int rsel = (lane & 7) | (lane & 8);      // ldmatrix row within 16
    const int csel = (lane >> 4) << 3;             // ldmatrix k-half select

    float acc[2][8][4] = {};

    auto issue = [&](int buf, int kc) {
#pragma unroll
        for (int i = 0; i < 2; i++) {              // A: 512 16B chunks
            int c = tid + i*256;
            int row = c >> 2, c8 = (c & 3)*8;
            const __half* gsrc = &g_poolh[(size_t)(bm*128 + row)*256 + kc + c8];
            uint32_t dst = (uint32_t)__cvta_generic_to_shared(&sA[buf][row*40 + c8]);
            asm volatile("cp.async.cg.shared.global [%0], [%1], 16;" :: "r"(dst), "l"(gsrc));
        }
#pragma unroll
        for (int i = 0; i < 2; i++) {              // B: 512 16B chunks
            int c = tid + i*256;
            int row = c >> 2, c8 = (c & 3)*8;
            const __half* gsrc = &g_wouth[(size_t)(bn*128 + row)*256 + kc + c8];
            uint32_t dst = (uint32_t)__cvta_generic_to_shared(&sB[buf][row*40 + c8]);
            asm volatile("cp.async.cg.shared.global [%0], [%1], 16;" :: "r"(dst), "l"(gsrc));
        }
        asm volatile("cp.async.commit_group;" ::: "memory");
    };

    issue(0, 0);
    for (int kt = 0; kt < 8; kt++) {
        if (kt + 1 < 8) {
            issue((kt+1) & 1, (kt+1)*32);
            asm volatile("cp.async.wait_group 1;" ::: "memory");
        } else {
            asm volatile("cp.async.wait_group 0;" ::: "memory");
        }
        __syncthreads();
        const __half* A  = sA[kt & 1];
        const __half* Bs = sB[kt & 1];
#pragma unroll
        for (int kk = 0; kk < 32; kk += 16) {
            uint32_t afr[2][4], bq[4][4];
#pragma unroll
            for (int mi = 0; mi < 2; mi++)
                ldsm_x4(afr[mi], &A[(wm*32 + mi*16 + rsel)*40 + kk + csel]);
#pragma unroll
            for (int nb = 0; nb < 4; nb++)
                ldsm_x4(bq[nb], &Bs[(wn*64 + nb*16 + rsel)*40 + kk + csel]);
#pragma unroll
            for (int mi = 0; mi < 2; mi++)
#pragma unroll
                for (int ni = 0; ni < 8; ni++) {
                    uint32_t bfr[2] = { bq[ni>>1][ni&1], bq[ni>>1][2 + (ni&1)] };
                    mma16816(acc[mi][ni], afr[mi], bfr);
                }
        }
        __syncthreads();   // buffer free before it is re-issued next iteration
    }
    const float inv = 1.0f/20.0f;
#pragma unroll
    for (int mi = 0; mi < 2; mi++) {
        int r = bm*128 + wm*32 + mi*16 + g;   // r = s*32 + b ; (r&31)+8 stays < 32
        int s = r >> 5, bb = r & 31;
        size_t base  = (size_t)bb*(size_t)S_*V_ + (size_t)s*V_;
        size_t base8 = base + (size_t)8*(size_t)S_*V_;
#pragma unroll
        for (int ni = 0; ni < 8; ni++) {
            int v = bn*128 + wn*64 + ni*8 + tg*2;
            float b0 = bout[v], b1v = bout[v+1];
            float2 lo = make_float2(acc[mi][ni][0]*inv + b0, acc[mi][ni][1]*inv + b1v);
            float2 hi = make_float2(acc[mi][ni][2]*inv + b0, acc[mi][ni][3]*inv + b1v);
            *(float2*)&out[base  + v] = lo;
            *(float2*)&out[base8 + v] = hi;
        }
    }
}

// ---------------- STDP fused: blockIdx.y = sel ----------------
// d[o,i] = sum_m (A_POST*post)[m,o]*(A_PRE*pre)[m,i], strictly increasing m
__global__ void k_stdp(float* __restrict__ outD1) {
    int sel = blockIdx.y;
    const float* Amat = (sel == 0) ? g_pm1 : (sel == 1 ? g_pm2 : g_pm3);
    const float* Bmat = (sel == 0) ? g_xmrep : (sel == 1 ? g_pm1 : g_pm2);
    int I = (sel == 0) ? E_ : H_;
    float* Dout = outD1 + (sel == 0 ? 0 : (sel == 1 ? (OFF_D2 - OFF_D1) : (OFF_D3 - OFF_D1)));
    int o = blockIdx.x;
    int i = threadIdx.x;
    if (i >= I) return;
    float acc = 0.f;
    for (int m = 0; m < NM_; m++) {
        float a = __fmul_rn(-0.003f, __ldg(&Amat[m*H_ + o]));  // A_POST * post
        float b = __fmul_rn( 0.005f, __ldg(&Bmat[m*I + i]));   // A_PRE * pre
        acc = fmaf(a, b, acc);
    }
    Dout[o*I + i] = acc;
}

// ---------------- launch ----------------
// RULE: never pass a __device__ symbol (g_*) as a kernel argument from here.
extern "C" void kernel_launch(void* const* d_in, const int* in_sizes, int n_in,
                              void* d_out, int out_size) {
    const int*   x     = (const int*)  d_in[0];
    const float* embed = (const float*)d_in[1];
    const float* W1    = (const float*)d_in[2];
    const float* b1    = (const float*)d_in[3];
    const float* W2    = (const float*)d_in[4];
    const float* b2    = (const float*)d_in[5];
    const float* W3    = (const float*)d_in[6];
    const float* b3    = (const float*)d_in[7];
    const float* Wout  = (const float*)d_in[8];
    const float* bout  = (const float*)d_in[9];
    float* out = (float*)d_out;

    (void)in_sizes; (void)n_in; (void)out_size;

    // merged prep: Wout fp16 + W2/W3 transpose
    k_prep<<<(V_*H_/2 + 255)/256, 256>>>(Wout, W2, W3);

    // layer-1 currents (raw fp32, sequential k) + batch-mean embeddings
    k_cur1 <<<S_, 256>>>(x, embed, W1, b1);
    k_xmrep<<<(NM_*E_ + 255)/256, 256>>>();

    // layer 1
    k_recur<1><<<256, 32>>>(out + OFF_REC1, out + OFF_MEM1);
    k_pm<<<NM_, 256>>>(0, out + OFF_REC1);
    // cur2 = spk1 @ W2.T + b2  (sparse, bit-exact sequential-k)
    k_gemm_sp<<<ROWS_/64, 256>>>(0, b2);
    // layer 2
    k_recur<2><<<256, 32>>>(out + OFF_REC2, out + OFF_MEM2);
    k_pm<<<NM_, 256>>>(1, out + OFF_REC2);
    // cur3 = spk2 @ W3.T + b3
    k_gemm_sp<<<ROWS_/64, 256>>>(1, b3);
    // layer 3 (also builds pooled spike counts)
    k_recur<3><<<256, 32>>>(out + OFF_REC3, out + OFF_MEM3);
    k_pm<<<NM_, 256>>>(2, out + OFF_REC3);

    // out = pooled @ Wout.T + bout  (fp16 tensor cores, cp.async pipelined)
    k_gemm_out<<<dim3(V_/128, RQ_/128), 256>>>(bout, out + OFF_OUT);

    // STDP (fused 3-in-1)
    k_stdp<<<dim3(H_, 3), 256>>>(out + OFF_D1);
}